// round 1
// baseline (speedup 1.0000x reference)
#include <cuda_runtime.h>

#define NNODES 100000
#define NEDGES 1600000
#define NREL 4

// Scratch (static __device__ arrays — allocation-free per harness rules)
__device__ __align__(16) float g_S1[NREL * NNODES * 16];  // 25.6 MB
__device__ __align__(16) float g_S2[NREL * NNODES * 16];  // 25.6 MB
__device__ __align__(16) float g_S3[NREL * NNODES * 32];  // 51.2 MB
__device__ int   g_cnt[NREL * NNODES];                    // 1.6 MB
__device__ __align__(16) float g_h1[NNODES * 16];
__device__ __align__(16) float g_h2[NNODES * 32];

// ---------------------------------------------------------------------------
// Per-(relation,dst) in-degree counts. Same for all three layers.
// ---------------------------------------------------------------------------
__global__ void count_kernel(const int* __restrict__ dst,
                             const int* __restrict__ et,
                             int* __restrict__ cnt, int n, int e) {
    int i = blockIdx.x * blockDim.x + threadIdx.x;
    if (i < e) atomicAdd(&cnt[et[i] * n + dst[i]], 1);
}

// ---------------------------------------------------------------------------
// Scatter: S[r, dst, :] += h[src, :]  via vectorized L2 reductions.
// One thread per (edge, float4-chunk): the DIN/4 threads of one edge cover a
// contiguous 64/128B row -> coalesced gather + coalesced RED target.
// ---------------------------------------------------------------------------
template <int DIN>
__global__ void scatter_kernel(const float* __restrict__ h,
                               const int* __restrict__ src,
                               const int* __restrict__ dst,
                               const int* __restrict__ et,
                               float* __restrict__ S, int n, int e) {
    constexpr int CH = DIN / 4;
    int t = blockIdx.x * blockDim.x + threadIdx.x;
    int ed = t / CH;
    int c  = t - ed * CH;
    if (ed >= e) return;
    int s = __ldg(src + ed);
    int d = __ldg(dst + ed);
    int r = __ldg(et + ed);
    const float4 v = *reinterpret_cast<const float4*>(h + (size_t)s * DIN + c * 4);
    float* p = S + ((size_t)r * n + d) * DIN + c * 4;
    asm volatile("red.global.add.v4.f32 [%0], {%1,%2,%3,%4};"
                 :: "l"(p), "f"(v.x), "f"(v.y), "f"(v.z), "f"(v.w)
                 : "memory");
}

// ---------------------------------------------------------------------------
// Combine: out[i] = bias + x[i]@root + sum_r (S[r,i]/max(cnt,1)) @ W_r
// One thread computes 4 consecutive outputs of one node; weight rows loaded as
// float4 (coalesced across the TPN threads of a node; W/root fit in L1).
// ---------------------------------------------------------------------------
template <int DIN, int DOUT, bool RELU>
__global__ void combine_kernel(const float* __restrict__ xin,
                               const float* __restrict__ S,
                               const int* __restrict__ cnt,
                               const float* __restrict__ W,
                               const float* __restrict__ root,
                               const float* __restrict__ bias,
                               float* __restrict__ out, int n) {
    constexpr int TPN = DOUT / 4;
    int t = blockIdx.x * blockDim.x + threadIdx.x;
    int node = t / TPN;
    if (node >= n) return;
    int oc = (t - node * TPN) * 4;

    float inv[NREL];
#pragma unroll
    for (int r = 0; r < NREL; r++) {
        int c = __ldg(cnt + r * n + node);
        inv[r] = 1.0f / (float)(c > 1 ? c : 1);
    }

    float4 acc = *reinterpret_cast<const float4*>(bias + oc);
    const float* xr = xin + (size_t)node * DIN;
    const float* sr = S + (size_t)node * DIN;

#pragma unroll
    for (int d = 0; d < DIN; d++) {
        float xv = __ldg(xr + d);
        float4 w = *reinterpret_cast<const float4*>(root + d * DOUT + oc);
        acc.x = fmaf(xv, w.x, acc.x);
        acc.y = fmaf(xv, w.y, acc.y);
        acc.z = fmaf(xv, w.z, acc.z);
        acc.w = fmaf(xv, w.w, acc.w);
#pragma unroll
        for (int r = 0; r < NREL; r++) {
            float mv = __ldg(sr + (size_t)r * n * DIN + d) * inv[r];
            float4 wr = *reinterpret_cast<const float4*>(
                W + ((size_t)r * DIN + d) * DOUT + oc);
            acc.x = fmaf(mv, wr.x, acc.x);
            acc.y = fmaf(mv, wr.y, acc.y);
            acc.z = fmaf(mv, wr.z, acc.z);
            acc.w = fmaf(mv, wr.w, acc.w);
        }
    }

    if (RELU) {
        acc.x = fmaxf(acc.x, 0.0f);
        acc.y = fmaxf(acc.y, 0.0f);
        acc.z = fmaxf(acc.z, 0.0f);
        acc.w = fmaxf(acc.w, 0.0f);
    }
    *reinterpret_cast<float4*>(out + (size_t)node * DOUT + oc) = acc;
}

// ---------------------------------------------------------------------------
// Launcher: zero scratch -> counts -> (scatter, combine) x 3 layers
// ---------------------------------------------------------------------------
extern "C" void kernel_launch(void* const* d_in, const int* in_sizes, int n_in,
                              void* d_out, int out_size) {
    const float* x     = (const float*)d_in[0];
    const int*   ei    = (const int*)d_in[1];   // [2, E]: src then dst
    const int*   et    = (const int*)d_in[2];
    const float* W1    = (const float*)d_in[3];
    const float* root1 = (const float*)d_in[4];
    const float* b1    = (const float*)d_in[5];
    const float* W2    = (const float*)d_in[6];
    const float* root2 = (const float*)d_in[7];
    const float* b2    = (const float*)d_in[8];
    const float* W3    = (const float*)d_in[9];
    const float* root3 = (const float*)d_in[10];
    const float* b3    = (const float*)d_in[11];
    float* out = (float*)d_out;

    const int n = in_sizes[0] / 16;
    const int e = in_sizes[2];
    const int* src = ei;
    const int* dst = ei + e;

    // Resolve scratch addresses (host API lookup, capture-safe)
    float *pS1, *pS2, *pS3, *ph1, *ph2;
    int* pcnt;
    cudaGetSymbolAddress((void**)&pS1, g_S1);
    cudaGetSymbolAddress((void**)&pS2, g_S2);
    cudaGetSymbolAddress((void**)&pS3, g_S3);
    cudaGetSymbolAddress((void**)&pcnt, g_cnt);
    cudaGetSymbolAddress((void**)&ph1, g_h1);
    cudaGetSymbolAddress((void**)&ph2, g_h2);

    // Zero accumulators (memset nodes in the graph)
    cudaMemsetAsync(pS1, 0, sizeof(float) * NREL * NNODES * 16);
    cudaMemsetAsync(pS2, 0, sizeof(float) * NREL * NNODES * 16);
    cudaMemsetAsync(pS3, 0, sizeof(float) * NREL * NNODES * 32);
    cudaMemsetAsync(pcnt, 0, sizeof(int) * NREL * NNODES);

    const int TB = 256;

    // Counts (shared across layers)
    count_kernel<<<(e + TB - 1) / TB, TB>>>(dst, et, pcnt, n, e);

    // Layer 1: 16 -> 16, relu
    {
        int tot = e * 4;
        scatter_kernel<16><<<(tot + TB - 1) / TB, TB>>>(x, src, dst, et, pS1, n, e);
        int ct = n * 4;
        combine_kernel<16, 16, true><<<(ct + TB - 1) / TB, TB>>>(
            x, pS1, pcnt, W1, root1, b1, ph1, n);
    }

    // Layer 2: 16 -> 32, relu
    {
        int tot = e * 4;
        scatter_kernel<16><<<(tot + TB - 1) / TB, TB>>>(ph1, src, dst, et, pS2, n, e);
        int ct = n * 8;
        combine_kernel<16, 32, true><<<(ct + TB - 1) / TB, TB>>>(
            ph1, pS2, pcnt, W2, root2, b2, ph2, n);
    }

    // Layer 3: 32 -> 64, no relu
    {
        int tot = e * 8;
        scatter_kernel<32><<<(tot + TB - 1) / TB, TB>>>(ph2, src, dst, et, pS3, n, e);
        int ct = n * 16;
        combine_kernel<32, 64, false><<<(ct + TB - 1) / TB, TB>>>(
            ph2, pS3, pcnt, W3, root3, b3, out, n);
    }
}

// round 2
// speedup vs baseline: 1.3741x; 1.3741x over previous
#include <cuda_runtime.h>

#define NNODES 100000
#define NEDGES 1600000
#define NREL 4

// Scratch (static __device__ arrays — allocation-free per harness rules)
__device__ __align__(16) float g_S1[NREL * NNODES * 16];  // 25.6 MB
__device__ __align__(16) float g_S2[NREL * NNODES * 16];  // 25.6 MB
__device__ __align__(16) float g_S3[NREL * NNODES * 32];  // 51.2 MB
__device__ int   g_cnt[NREL * NNODES];                    // 1.6 MB
__device__ __align__(16) float g_h1[NNODES * 16];
__device__ __align__(16) float g_h2[NNODES * 32];

// ---------------------------------------------------------------------------
// f32x2 packed-FMA helpers (sm_100+)
// ---------------------------------------------------------------------------
__device__ __forceinline__ void ffma2(unsigned long long& acc,
                                      unsigned long long a,
                                      unsigned long long b) {
    asm("fma.rn.f32x2 %0, %1, %2, %0;" : "+l"(acc) : "l"(a), "l"(b));
}
__device__ __forceinline__ unsigned long long bcast2(float v) {
    unsigned long long r;
    unsigned int u = __float_as_uint(v);
    asm("mov.b64 %0, {%1, %1};" : "=l"(r) : "r"(u));
    return r;
}

// Multiply-accumulate one weight row (DOUT floats, broadcast from smem) by a
// scalar input value into packed accumulators.
template <int DOUT>
__device__ __forceinline__ void mac_row(unsigned long long* acc,
                                        const float* __restrict__ wrow,
                                        float v) {
    unsigned long long v2 = bcast2(v);
#pragma unroll
    for (int j = 0; j < DOUT / 4; j++) {
        ulonglong2 w = *reinterpret_cast<const ulonglong2*>(wrow + 4 * j);
        ffma2(acc[2 * j], v2, w.x);
        ffma2(acc[2 * j + 1], v2, w.y);
    }
}

// ---------------------------------------------------------------------------
// Scatter: S[r, dst, :] += h[src, :] via vectorized L2 reductions.
// One thread per (edge, float4-chunk). Optionally fuses per-(r,dst) counting.
// ---------------------------------------------------------------------------
template <int DIN, bool COUNT>
__global__ void scatter_kernel(const float* __restrict__ h,
                               const int* __restrict__ src,
                               const int* __restrict__ dst,
                               const int* __restrict__ et,
                               float* __restrict__ S,
                               int* __restrict__ cnt, int n, int e) {
    constexpr int CH = DIN / 4;
    int t = blockIdx.x * blockDim.x + threadIdx.x;
    int ed = t / CH;
    int c  = t - ed * CH;
    if (ed >= e) return;
    int s = __ldg(src + ed);
    int d = __ldg(dst + ed);
    int r = __ldg(et + ed);
    const float4 v = *reinterpret_cast<const float4*>(h + (size_t)s * DIN + c * 4);
    float* p = S + ((size_t)r * n + d) * DIN + c * 4;
    asm volatile("red.global.add.v4.f32 [%0], {%1,%2,%3,%4};"
                 :: "l"(p), "f"(v.x), "f"(v.y), "f"(v.z), "f"(v.w)
                 : "memory");
    if (COUNT && c == 0) atomicAdd(cnt + r * n + d, 1);
}

// ---------------------------------------------------------------------------
// Combine: out[i] = bias + x[i]@root + sum_r (S[r,i]/max(cnt,1)) @ W_r
// One thread per node, ALL DOUT outputs in packed f32x2 registers. Weights
// staged in smem and read via broadcast LDS.128. Inputs read exactly once.
// ---------------------------------------------------------------------------
template <int DIN, int DOUT, bool RELU>
__global__ void __launch_bounds__(128)
combine_kernel(const float* __restrict__ xin,
               const float* __restrict__ S,
               const int* __restrict__ cnt,
               const float* __restrict__ W,     // [R, DIN, DOUT]
               const float* __restrict__ root,  // [DIN, DOUT]
               const float* __restrict__ bias,  // [DOUT]
               float* __restrict__ out, int n) {
    __shared__ __align__(16) float sw[5 * DIN * DOUT];
    const int tid = threadIdx.x;
    for (int i = tid; i < DIN * DOUT; i += 128) sw[i] = root[i];
    for (int i = tid; i < NREL * DIN * DOUT; i += 128) sw[DIN * DOUT + i] = W[i];
    __syncthreads();

    const int node = blockIdx.x * 128 + tid;
    if (node >= n) return;

    unsigned long long acc[DOUT / 2];
#pragma unroll
    for (int j = 0; j < DOUT / 2; j++)
        acc[j] = reinterpret_cast<const unsigned long long*>(bias)[j];

    float inv[NREL];
#pragma unroll
    for (int r = 0; r < NREL; r++) {
        int c = __ldg(cnt + r * n + node);
        inv[r] = 1.0f / (float)(c > 1 ? c : 1);
    }

#pragma unroll
    for (int rb = 0; rb < 5; rb++) {
        const float scale = (rb == 0) ? 1.0f : inv[rb - 1];
        const float4* __restrict__ base = reinterpret_cast<const float4*>(
            (rb == 0) ? xin + (size_t)node * DIN
                      : S + ((size_t)(rb - 1) * n + node) * DIN);
        const float* __restrict__ wr = sw + rb * DIN * DOUT;
        for (int c4 = 0; c4 < DIN / 4; c4++) {
            float4 v4 = __ldg(base + c4);
            mac_row<DOUT>(acc, wr + (c4 * 4 + 0) * DOUT, v4.x * scale);
            mac_row<DOUT>(acc, wr + (c4 * 4 + 1) * DOUT, v4.y * scale);
            mac_row<DOUT>(acc, wr + (c4 * 4 + 2) * DOUT, v4.z * scale);
            mac_row<DOUT>(acc, wr + (c4 * 4 + 3) * DOUT, v4.w * scale);
        }
    }

    float* op = out + (size_t)node * DOUT;
#pragma unroll
    for (int j = 0; j < DOUT / 2; j++) {
        float2 f = *reinterpret_cast<float2*>(&acc[j]);
        if (RELU) {
            f.x = fmaxf(f.x, 0.0f);
            f.y = fmaxf(f.y, 0.0f);
        }
        reinterpret_cast<float2*>(op)[j] = f;
    }
}

// ---------------------------------------------------------------------------
// Launcher: zero scratch -> (scatter[+count], combine) x 3 layers
// ---------------------------------------------------------------------------
extern "C" void kernel_launch(void* const* d_in, const int* in_sizes, int n_in,
                              void* d_out, int out_size) {
    const float* x     = (const float*)d_in[0];
    const int*   ei    = (const int*)d_in[1];   // [2, E]: src then dst
    const int*   et    = (const int*)d_in[2];
    const float* W1    = (const float*)d_in[3];
    const float* root1 = (const float*)d_in[4];
    const float* b1    = (const float*)d_in[5];
    const float* W2    = (const float*)d_in[6];
    const float* root2 = (const float*)d_in[7];
    const float* b2    = (const float*)d_in[8];
    const float* W3    = (const float*)d_in[9];
    const float* root3 = (const float*)d_in[10];
    const float* b3    = (const float*)d_in[11];
    float* out = (float*)d_out;

    const int n = in_sizes[0] / 16;
    const int e = in_sizes[2];
    const int* src = ei;
    const int* dst = ei + e;

    float *pS1, *pS2, *pS3, *ph1, *ph2;
    int* pcnt;
    cudaGetSymbolAddress((void**)&pS1, g_S1);
    cudaGetSymbolAddress((void**)&pS2, g_S2);
    cudaGetSymbolAddress((void**)&pS3, g_S3);
    cudaGetSymbolAddress((void**)&pcnt, g_cnt);
    cudaGetSymbolAddress((void**)&ph1, g_h1);
    cudaGetSymbolAddress((void**)&ph2, g_h2);

    cudaMemsetAsync(pS1, 0, sizeof(float) * NREL * NNODES * 16);
    cudaMemsetAsync(pS2, 0, sizeof(float) * NREL * NNODES * 16);
    cudaMemsetAsync(pS3, 0, sizeof(float) * NREL * NNODES * 32);
    cudaMemsetAsync(pcnt, 0, sizeof(int) * NREL * NNODES);

    const int TB = 256;
    const int CB = 128;
    const int cgrid = (n + CB - 1) / CB;

    // Layer 1: 16 -> 16, relu (scatter fuses the degree count)
    {
        int tot = e * 4;
        scatter_kernel<16, true><<<(tot + TB - 1) / TB, TB>>>(
            x, src, dst, et, pS1, pcnt, n, e);
        combine_kernel<16, 16, true><<<cgrid, CB>>>(
            x, pS1, pcnt, W1, root1, b1, ph1, n);
    }

    // Layer 2: 16 -> 32, relu
    {
        int tot = e * 4;
        scatter_kernel<16, false><<<(tot + TB - 1) / TB, TB>>>(
            ph1, src, dst, et, pS2, pcnt, n, e);
        combine_kernel<16, 32, true><<<cgrid, CB>>>(
            ph1, pS2, pcnt, W2, root2, b2, ph2, n);
    }

    // Layer 3: 32 -> 64, no relu
    {
        int tot = e * 8;
        scatter_kernel<32, false><<<(tot + TB - 1) / TB, TB>>>(
            ph2, src, dst, et, pS3, pcnt, n, e);
        combine_kernel<32, 64, false><<<cgrid, CB>>>(
            ph2, pS3, pcnt, W3, root3, b3, out, n);
    }
}